// round 12
// baseline (speedup 1.0000x reference)
#include <cuda_runtime.h>
#include <math.h>
#include <stdint.h>

#define Bz   64
#define Tt   512
#define Fin  128
#define Un   1024
#define G4   4096
#define NCLS 16
#define KC   32
#define GRID 128

// persistent state
__device__ float g_h0[2][Bz*Un];
__device__ float g_c0[Bz*Un];
__device__ float g_h1[2][Bz*Un];
__device__ float g_c1[Bz*Un];
__device__ __align__(16) float2 g_part0[Bz*GRID];
__device__ __align__(16) float2 g_part1[Bz*GRID];
__device__ unsigned g_count;
__device__ unsigned g_gen;

union U64F2 { unsigned long long u; float2 f; };

__device__ __forceinline__ float sigm(float x){ return 1.f/(1.f+expf(-x)); }

// grid-wide sense barrier (all 128 blocks resident => safe)
__device__ __forceinline__ void gridbar(unsigned &gen){
    __syncthreads();
    if (threadIdx.x == 0){
        __threadfence();
        unsigned arr = atomicAdd(&g_count, 1u);
        if (arr == (unsigned)(gridDim.x - 1)){
            g_count = 0u;
            __threadfence();
            atomicExch(&g_gen, gen + 1u);
        } else {
            unsigned cur;
            do {
                asm volatile("ld.acquire.gpu.global.u32 %0, [%1];" : "=r"(cur) : "l"(&g_gen));
            } while (cur == gen);
        }
    }
    gen++;
    __syncthreads();
}

// one K-chunk: per thread 2 rows x 4 cols, packed f32x2 FMAs
// sA: [KC][66] natural rows (64 + pad2). sU: [KC][32] natural cols.
__device__ __forceinline__ void compute_chunk(
    const float* __restrict__ sA, const float* __restrict__ sU,
    int pg, int cg, unsigned long long acc[4])
{
    const float* pa = sA + 2*pg;
    const float* pu = sU + 4*cg;
#pragma unroll
    for (int k = 0; k < KC; k++){
        float2 av = *reinterpret_cast<const float2*>(pa + k*66);
        ulonglong2 uv = *reinterpret_cast<const ulonglong2*>(pu + k*32);
        unsigned long long d0, d1;
        asm("mov.b64 %0,{%1,%1};" : "=l"(d0) : "f"(av.x));
        asm("mov.b64 %0,{%1,%1};" : "=l"(d1) : "f"(av.y));
        asm("fma.rn.f32x2 %0,%1,%2,%0;" : "+l"(acc[0]) : "l"(d0), "l"(uv.x));
        asm("fma.rn.f32x2 %0,%1,%2,%0;" : "+l"(acc[1]) : "l"(d0), "l"(uv.y));
        asm("fma.rn.f32x2 %0,%1,%2,%0;" : "+l"(acc[2]) : "l"(d1), "l"(uv.x));
        asm("fma.rn.f32x2 %0,%1,%2,%0;" : "+l"(acc[3]) : "l"(d1), "l"(uv.y));
    }
}

__global__ void initState(){
    int i = blockIdx.x*blockDim.x + threadIdx.x;
    if (i == 0){ g_count = 0u; g_gen = 0u; }
    int stride = gridDim.x*blockDim.x;
    for (int j = i; j < Bz*Un; j += stride){
        g_h0[0][j]=0.f; g_h0[1][j]=0.f; g_c0[j]=0.f;
        g_h1[0][j]=0.f; g_h1[1][j]=0.f; g_c1[j]=0.f;
    }
}

__global__ void __launch_bounds__(256,1) lstm_persistent(
    const float* __restrict__ x,
    const float* __restrict__ W0, const float* __restrict__ U0, const float* __restrict__ b0,
    const float* __restrict__ g0, const float* __restrict__ be0,
    const float* __restrict__ W1, const float* __restrict__ U1, const float* __restrict__ b1,
    const float* __restrict__ g1, const float* __restrict__ be1,
    const float* __restrict__ Wfc, const float* __restrict__ bfc,
    float* __restrict__ out)
{
    __shared__ __align__(16) float sPool[6272];   // sA0|sA1|sU0|sU1 ; aliased by sZ / sO
    __shared__ float s_mu[64], s_rs[64];
    __shared__ float s_logit[16];
    __shared__ float s_st[2];

    float* sA0 = sPool;                 // 2112 floats (32*66)
    float* sA1 = sPool + 2112;
    float* sU0 = sPool + 4224;          // 1024 floats (32*32)
    float* sU1 = sPool + 5248;
    float* sZ  = sPool;                 // epilogue alias (64*34 = 2176 floats)
    float* sO  = sPool;                 // phase-C alias (1024 floats)

    const int tid  = threadIdx.x;
    const int b    = blockIdx.x;
    const int u0   = b * 8;
    const int cg   = tid & 7;           // 4 cols: 4cg..4cg+3
    const int pg   = tid >> 3;          // 2 rows: 2pg, 2pg+1
    const int lane = tid & 31, warp = tid >> 5;

    // staging maps
    const int kA  = tid & 31;           // A: lane varies k
    const int rA0 = tid >> 5;           // rows rA0 + 8p (p<8)
    const int cS  = tid & 31;           // U: lane varies col
    const int kU0 = tid >> 5;           // rows kU0 + 8p (p<4)
    const int gcS = ((cS >> 3) << 10) + u0 + (cS & 7);

    const int ci0 = 4*cg;
    const int gc  = ((ci0 >> 3) << 10) + u0 + (ci0 & 7);   // contiguous 4 cols
    float bias0[4], bias1[4];
#pragma unroll
    for (int j=0;j<4;j++){ bias0[j] = __ldg(b0 + gc + j); bias1[j] = __ldg(b1 + gc + j); }

    unsigned gen = 0;
    float rAr[8], rUr[4];

#pragma unroll 1
    for (int t = 0; t < Tt; t++){
        const int ping = t & 1;
        const float* h0_in  = g_h0[ping];
        float*       h0_out = g_h0[ping^1];
        const float* h1_in  = g_h1[ping];
        float*       h1_out = g_h1[ping^1];

        // ============== phase A : layer-0 GEMM + gates ==============
        {
            unsigned long long acc[4];
            { U64F2 v; v.f = make_float2(bias0[0], bias0[1]); acc[0]=v.u;
                       v.f = make_float2(bias0[2], bias0[3]); acc[1]=v.u;
              acc[2]=acc[0]; acc[3]=acc[1]; }

            auto ldgA = [&](int cc){
                if (cc < 32){
                    int k = cc*KC + kA;
#pragma unroll
                    for (int p=0;p<8;p++) rAr[p] = __ldcg(h0_in + (rA0+8*p)*Un + k);
                    const float* ub = U0 + (size_t)(cc*KC)*G4 + gcS;
#pragma unroll
                    for (int p=0;p<4;p++) rUr[p] = __ldg(ub + (size_t)(kU0+8*p)*G4);
                } else {
                    int j = cc - 32;
                    int k = j*KC + kA;
#pragma unroll
                    for (int p=0;p<8;p++) rAr[p] = __ldg(x + ((size_t)(rA0+8*p)*Tt + t)*Fin + k);
                    const float* ub = W0 + (size_t)(j*KC)*G4 + gcS;
#pragma unroll
                    for (int p=0;p<4;p++) rUr[p] = __ldg(ub + (size_t)(kU0+8*p)*G4);
                }
            };
            auto stsA = [&](float* sa, float* su){
#pragma unroll
                for (int p=0;p<8;p++) sa[kA*66 + rA0 + 8*p] = rAr[p];
#pragma unroll
                for (int p=0;p<4;p++) su[(kU0+8*p)*32 + cS] = rUr[p];
            };

            ldgA(0); stsA(sA0, sU0);
            __syncthreads();
#pragma unroll 1
            for (int cc=0; cc<36; cc++){
                const float* ca = (cc&1)? sA1 : sA0;
                const float* cu = (cc&1)? sU1 : sU0;
                if (cc+1 < 36) ldgA(cc+1);
                compute_chunk(ca, cu, pg, cg, acc);
                if (cc+1 < 36) stsA((cc&1)? sA0:sA1, (cc&1)? sU0:sU1);
                __syncthreads();
            }
            {
                U64F2 v; int r0 = 2*pg;
                v.u=acc[0]; *reinterpret_cast<float2*>(sZ + r0*34 + ci0)       = v.f;
                v.u=acc[1]; *reinterpret_cast<float2*>(sZ + r0*34 + ci0 + 2)   = v.f;
                v.u=acc[2]; *reinterpret_cast<float2*>(sZ + (r0+1)*34 + ci0)   = v.f;
                v.u=acc[3]; *reinterpret_cast<float2*>(sZ + (r0+1)*34 + ci0+2) = v.f;
            }
            __syncthreads();
#pragma unroll
            for (int it=0; it<2; it++){
                int idx = tid + it*256;
                int r = idx >> 3, uu = idx & 7;
                float zi = sZ[r*34 + uu];
                float zf = sZ[r*34 + 8 + uu];
                float zg = sZ[r*34 + 16 + uu];
                float zo = sZ[r*34 + 24 + uu];
                float gi = sigm(zi), gf = sigm(zf), gg = tanhf(zg), go = sigm(zo);
                int gidx = r*Un + u0 + uu;
                float cn = gf * g_c0[gidx] + gi*gg;
                g_c0[gidx] = cn;
                float h = go * tanhf(cn);
                __stcg(h0_out + gidx, h);
                float s = h, q = h*h;
                s += __shfl_down_sync(0xffffffffu, s, 4, 8);
                q += __shfl_down_sync(0xffffffffu, q, 4, 8);
                s += __shfl_down_sync(0xffffffffu, s, 2, 8);
                q += __shfl_down_sync(0xffffffffu, q, 2, 8);
                s += __shfl_down_sync(0xffffffffu, s, 1, 8);
                q += __shfl_down_sync(0xffffffffu, q, 1, 8);
                if ((tid & 7) == 0)
                    __stcg(&g_part0[r*GRID + b], make_float2(s, q));
            }
        }
        gridbar(gen);

        // ============== phase B : LN(h0) + layer-1 GEMM + gates ==============
        {
            // reduce layer-0 LN partials -> s_mu/s_rs (warp w owns rows 8w..8w+7)
#pragma unroll
            for (int rr=0; rr<8; rr++){
                int r = warp*8 + rr;
                const float4* p = reinterpret_cast<const float4*>(g_part0 + r*GRID);
                float4 A  = __ldcg(p + lane*2);
                float4 Bv = __ldcg(p + lane*2 + 1);
                float s = A.x + A.z + Bv.x + Bv.z;
                float q = A.y + A.w + Bv.y + Bv.w;
#pragma unroll
                for (int o=16;o;o>>=1){
                    s += __shfl_down_sync(0xffffffffu, s, o);
                    q += __shfl_down_sync(0xffffffffu, q, o);
                }
                if (lane == 0){
                    float mu  = s * (1.f/1024.f);
                    float var = fmaxf(q * (1.f/1024.f) - mu*mu, 0.f);
                    s_mu[r] = mu; s_rs[r] = rsqrtf(var + 1e-3f);
                }
            }
            __syncthreads();

            unsigned long long acc[4];
            { U64F2 v; v.f = make_float2(bias1[0], bias1[1]); acc[0]=v.u;
                       v.f = make_float2(bias1[2], bias1[3]); acc[1]=v.u;
              acc[2]=acc[0]; acc[3]=acc[1]; }

            float gk = 0.f, bek = 0.f;
            auto ldgB = [&](int cc){
                if (cc < 32){
                    int k = cc*KC + kA;
#pragma unroll
                    for (int p=0;p<8;p++) rAr[p] = __ldcg(h1_in + (rA0+8*p)*Un + k);
                    const float* ub = U1 + (size_t)(cc*KC)*G4 + gcS;
#pragma unroll
                    for (int p=0;p<4;p++) rUr[p] = __ldg(ub + (size_t)(kU0+8*p)*G4);
                } else {
                    int j = cc - 32;
                    int k = j*KC + kA;
                    gk = __ldg(g0 + k); bek = __ldg(be0 + k);
#pragma unroll
                    for (int p=0;p<8;p++) rAr[p] = __ldcg(h0_out + (rA0+8*p)*Un + k);
                    const float* ub = W1 + (size_t)(j*KC)*G4 + gcS;
#pragma unroll
                    for (int p=0;p<4;p++) rUr[p] = __ldg(ub + (size_t)(kU0+8*p)*G4);
                }
            };
            auto stsB = [&](float* sa, float* su, bool norm){
                if (norm){
#pragma unroll
                    for (int p=0;p<8;p++){
                        int r = rA0 + 8*p;
                        sa[kA*66 + r] = (rAr[p] - s_mu[r]) * s_rs[r] * gk + bek;
                    }
                } else {
#pragma unroll
                    for (int p=0;p<8;p++) sa[kA*66 + rA0 + 8*p] = rAr[p];
                }
#pragma unroll
                for (int p=0;p<4;p++) su[(kU0+8*p)*32 + cS] = rUr[p];
            };

            ldgB(0); stsB(sA0, sU0, false);
            __syncthreads();
#pragma unroll 1
            for (int cc=0; cc<64; cc++){
                const float* ca = (cc&1)? sA1 : sA0;
                const float* cu = (cc&1)? sU1 : sU0;
                if (cc+1 < 64) ldgB(cc+1);
                compute_chunk(ca, cu, pg, cg, acc);
                if (cc+1 < 64) stsB((cc&1)? sA0:sA1, (cc&1)? sU0:sU1, (cc+1) >= 32);
                __syncthreads();
            }
            {
                U64F2 v; int r0 = 2*pg;
                v.u=acc[0]; *reinterpret_cast<float2*>(sZ + r0*34 + ci0)       = v.f;
                v.u=acc[1]; *reinterpret_cast<float2*>(sZ + r0*34 + ci0 + 2)   = v.f;
                v.u=acc[2]; *reinterpret_cast<float2*>(sZ + (r0+1)*34 + ci0)   = v.f;
                v.u=acc[3]; *reinterpret_cast<float2*>(sZ + (r0+1)*34 + ci0+2) = v.f;
            }
            __syncthreads();
#pragma unroll
            for (int it=0; it<2; it++){
                int idx = tid + it*256;
                int r = idx >> 3, uu = idx & 7;
                float zi = sZ[r*34 + uu];
                float zf = sZ[r*34 + 8 + uu];
                float zg = sZ[r*34 + 16 + uu];
                float zo = sZ[r*34 + 24 + uu];
                float gi = sigm(zi), gf = sigm(zf), gg = tanhf(zg), go = sigm(zo);
                int gidx = r*Un + u0 + uu;
                float cn = gf * g_c1[gidx] + gi*gg;
                g_c1[gidx] = cn;
                float h = go * tanhf(cn);
                __stcg(h1_out + gidx, h);
                float s = h, q = h*h;
                s += __shfl_down_sync(0xffffffffu, s, 4, 8);
                q += __shfl_down_sync(0xffffffffu, q, 4, 8);
                s += __shfl_down_sync(0xffffffffu, s, 2, 8);
                q += __shfl_down_sync(0xffffffffu, q, 2, 8);
                s += __shfl_down_sync(0xffffffffu, s, 1, 8);
                q += __shfl_down_sync(0xffffffffu, q, 1, 8);
                if ((tid & 7) == 0)
                    __stcg(&g_part1[r*GRID + b], make_float2(s, q));
            }
        }
        gridbar(gen);

        // ============== phase C : LN(h1) + FC + softmax (blocks 0..63) ==============
        if (b < 64){
            const float* h = h1_out + b*Un;
            float v[4];
#pragma unroll
            for (int i=0;i<4;i++) v[i] = __ldcg(h + tid + i*256);
            if (warp == 0){
                const float4* p = reinterpret_cast<const float4*>(g_part1 + b*GRID);
                float4 A  = __ldcg(p + lane*2);
                float4 Bv = __ldcg(p + lane*2 + 1);
                float s = A.x + A.z + Bv.x + Bv.z;
                float q = A.y + A.w + Bv.y + Bv.w;
#pragma unroll
                for (int o=16;o;o>>=1){
                    s += __shfl_down_sync(0xffffffffu, s, o);
                    q += __shfl_down_sync(0xffffffffu, q, o);
                }
                if (lane == 0){
                    float mu  = s * (1.f/1024.f);
                    float var = fmaxf(q * (1.f/1024.f) - mu*mu, 0.f);
                    s_st[0] = mu; s_st[1] = rsqrtf(var + 1e-3f);
                }
            }
            __syncthreads();
            float mu = s_st[0], rs = s_st[1];
#pragma unroll
            for (int i=0;i<4;i++){
                int k = tid + i*256;
                sO[k] = (v[i]-mu)*rs*__ldg(g1+k) + __ldg(be1+k);
            }
            __syncthreads();
            {
                float l0 = 0.f, l1 = 0.f;
#pragma unroll 4
                for (int k=lane; k<Un; k+=32){
                    float o = sO[k];
                    l0 += o * __ldg(Wfc + k*NCLS + 2*warp);
                    l1 += o * __ldg(Wfc + k*NCLS + 2*warp + 1);
                }
#pragma unroll
                for (int o=16;o;o>>=1){
                    l0 += __shfl_down_sync(0xffffffffu, l0, o);
                    l1 += __shfl_down_sync(0xffffffffu, l1, o);
                }
                if (lane == 0){
                    s_logit[2*warp]   = l0 + __ldg(bfc + 2*warp);
                    s_logit[2*warp+1] = l1 + __ldg(bfc + 2*warp+1);
                }
            }
            __syncthreads();
            if (tid < NCLS){
                float m = -1e30f;
#pragma unroll
                for (int j=0;j<NCLS;j++) m = fmaxf(m, s_logit[j]);
                float ss = 0.f;
#pragma unroll
                for (int j=0;j<NCLS;j++) ss += expf(s_logit[j]-m);
                out[((size_t)b*Tt + t)*NCLS + tid] = expf(s_logit[tid]-m) / ss;
            }
            __syncthreads();   // protect sO before next-t staging reuses sPool
        }
    }
}

extern "C" void kernel_launch(void* const* d_in, const int* in_sizes, int n_in,
                              void* d_out, int out_size)
{
    const float* x   = (const float*)d_in[0];
    const float* W0  = (const float*)d_in[1];
    const float* U0  = (const float*)d_in[2];
    const float* b0  = (const float*)d_in[3];
    const float* g0  = (const float*)d_in[4];
    const float* be0 = (const float*)d_in[5];
    const float* W1  = (const float*)d_in[6];
    const float* U1  = (const float*)d_in[7];
    const float* b1  = (const float*)d_in[8];
    const float* g1  = (const float*)d_in[9];
    const float* be1 = (const float*)d_in[10];
    const float* Wfc = (const float*)d_in[11];
    const float* bfc = (const float*)d_in[12];
    float* out = (float*)d_out;

    initState<<<128, 512>>>();
    lstm_persistent<<<GRID, 256>>>(x, W0, U0, b0, g0, be0,
                                   W1, U1, b1, g1, be1, Wfc, bfc, out);
}

// round 13
// speedup vs baseline: 1.7547x; 1.7547x over previous
#include <cuda_runtime.h>
#include <cuda_bf16.h>
#include <math.h>
#include <stdint.h>

#define Bz   64
#define Tt   512
#define Fin  128
#define Un   1024
#define G4   4096
#define NCLS 16
#define GRID 64
#define KT   64

#define ROWS72   72
#define MATEL    4608          // 64*72
#define OFF_AHI  0
#define OFF_ALO  4608
#define OFF_BHI  9216
#define OFF_BLO  13824
#define BUFEL    18432
#define SMEM_DYN (2*BUFEL*2)   // 73728 bytes

// weights: hi/lo split, transposed to [n][k]
__device__ __nv_bfloat16 g_U0t[2][(size_t)G4*Un];
__device__ __nv_bfloat16 g_W1t[2][(size_t)G4*Un];
__device__ __nv_bfloat16 g_U1t[2][(size_t)G4*Un];
__device__ __nv_bfloat16 g_W0t[2][(size_t)G4*Fin];

// state
__device__ __nv_bfloat16 g_h0b[2][2][Bz*Un];   // [ping][hi/lo]
__device__ __nv_bfloat16 g_h1b[2][2][Bz*Un];
__device__ float g_h1f[Bz*Un];
__device__ float g_c0[Bz*Un];
__device__ float g_c1[Bz*Un];
__device__ __align__(16) float2 g_part0[Bz*GRID];
__device__ __align__(16) float2 g_part1[Bz*GRID];
__device__ unsigned g_count, g_gen;

__device__ __forceinline__ float sigm(float x){ return 1.f/(1.f+expf(-x)); }

__device__ __forceinline__ void gridbar(unsigned &gen){
    __syncthreads();
    if (threadIdx.x == 0){
        __threadfence();
        unsigned arr = atomicAdd(&g_count, 1u);
        if (arr == (unsigned)(GRID - 1)){
            g_count = 0u;
            __threadfence();
            atomicExch(&g_gen, gen + 1u);
        } else {
            unsigned cur;
            do { asm volatile("ld.acquire.gpu.global.u32 %0,[%1];" : "=r"(cur) : "l"(&g_gen)); }
            while (cur == gen);
        }
    }
    gen++;
    __syncthreads();
}

__device__ __forceinline__ void mma16816(float* d, const unsigned* a, const unsigned* b){
    asm("mma.sync.aligned.m16n8k16.row.col.f32.bf16.bf16.f32 "
        "{%0,%1,%2,%3},{%4,%5,%6,%7},{%8,%9},{%0,%1,%2,%3};"
        : "+f"(d[0]),"+f"(d[1]),"+f"(d[2]),"+f"(d[3])
        : "r"(a[0]),"r"(a[1]),"r"(a[2]),"r"(a[3]),"r"(b[0]),"r"(b[1]));
}
__device__ __forceinline__ void ldsm4(unsigned* r, unsigned addr){
    asm volatile("ldmatrix.sync.aligned.m8n8.x4.shared.b16 {%0,%1,%2,%3},[%4];"
        : "=r"(r[0]),"=r"(r[1]),"=r"(r[2]),"=r"(r[3]) : "r"(addr));
}
__device__ __forceinline__ unsigned pk2(float a, float b){
    __nv_bfloat162 t = __floats2bfloat162_rn(a, b);
    return *reinterpret_cast<unsigned*>(&t);
}
__device__ __forceinline__ void up2(unsigned u, float &a, float &b){
    __nv_bfloat162 t; *reinterpret_cast<unsigned*>(&t) = u;
    a = __bfloat162float(t.x); b = __bfloat162float(t.y);
}
__device__ __forceinline__ void split8(const float* f, uint4 &H, uint4 &L){
    float hf[8], lf[8];
#pragma unroll
    for (int i=0;i<8;i++){
        __nv_bfloat16 h = __float2bfloat16(f[i]);
        hf[i] = __bfloat162float(h); lf[i] = f[i] - hf[i];
    }
    H = make_uint4(pk2(hf[0],hf[1]),pk2(hf[2],hf[3]),pk2(hf[4],hf[5]),pk2(hf[6],hf[7]));
    L = make_uint4(pk2(lf[0],lf[1]),pk2(lf[2],lf[3]),pk2(lf[4],lf[5]),pk2(lf[6],lf[7]));
}

__global__ void initState(){
    int i = blockIdx.x*blockDim.x + threadIdx.x;
    if (i == 0){ g_count = 0u; g_gen = 0u; }
    int stride = gridDim.x*blockDim.x;
    __nv_bfloat16 z = __float2bfloat16(0.f);
    for (int j=i; j<Bz*Un; j+=stride){
        g_h0b[0][0][j]=z; g_h0b[0][1][j]=z; g_h1b[0][0][j]=z; g_h1b[0][1][j]=z;
        g_c0[j]=0.f; g_c1[j]=0.f;
    }
}

// transpose + hi/lo split: src [K, 4096] -> dst [4096, K] bf16 hi/lo
__global__ void prepSplit(const float* __restrict__ src, int K, int which){
    __shared__ float tile[32][33];
    __nv_bfloat16 *dh, *dl;
    if      (which==0){ dh=g_U0t[0]; dl=g_U0t[1]; }
    else if (which==1){ dh=g_W1t[0]; dl=g_W1t[1]; }
    else if (which==2){ dh=g_U1t[0]; dl=g_U1t[1]; }
    else              { dh=g_W0t[0]; dl=g_W0t[1]; }
    int n0 = blockIdx.x*32, k0 = blockIdx.y*32;
    int tx = threadIdx.x, ty = threadIdx.y;   // 32 x 8
#pragma unroll
    for (int j=0;j<4;j++)
        tile[ty+8*j][tx] = src[(size_t)(k0+ty+8*j)*G4 + n0 + tx];
    __syncthreads();
#pragma unroll
    for (int j=0;j<4;j++){
        int n = ty + 8*j;
        float v = tile[tx][n];
        __nv_bfloat16 h = __float2bfloat16(v);
        size_t o = (size_t)(n0+n)*K + k0 + tx;
        dh[o] = h; dl[o] = __float2bfloat16(v - __bfloat162float(h));
    }
}

__global__ void __launch_bounds__(256,1) lstm_persistent(
    const float* __restrict__ x,
    const float* __restrict__ b0, const float* __restrict__ g0, const float* __restrict__ be0,
    const float* __restrict__ b1, const float* __restrict__ g1, const float* __restrict__ be1,
    const float* __restrict__ Wfc, const float* __restrict__ bfc,
    float* __restrict__ out)
{
    extern __shared__ __align__(16) char s_pool[];
    __nv_bfloat16* s_bf = reinterpret_cast<__nv_bfloat16*>(s_pool);
    float* sZf = reinterpret_cast<float*>(s_pool);
    __shared__ float s_mu[64], s_rs[64];
    __shared__ float s_logit[16];
    __shared__ float s_st[2];

    const unsigned sbase = (unsigned)__cvta_generic_to_shared(s_pool);
    const int tid  = threadIdx.x;
    const int b    = blockIdx.x;
    const int u0   = b * 16;
    const int lane = tid & 31, warp = tid >> 5;

    const int wm = warp & 1, wn = warp >> 1;
    const int rowbase = 32*wm, n0w = 16*wn;
    const int laneA_row = lane & 15;
    const int laneA_k   = (lane >> 4) << 3;
    const int laneB_n   = (lane & 7) + ((lane >> 4) << 3);
    const int laneB_k   = ((lane >> 3) & 1) << 3;

    const int ko = tid & 7;
    const int rr = tid >> 3;
    const int uu = tid & 15;

    const float bI0=__ldg(b0+u0+uu), bF0=__ldg(b0+Un+u0+uu), bG0=__ldg(b0+2*Un+u0+uu), bO0=__ldg(b0+3*Un+u0+uu);
    const float bI1=__ldg(b1+u0+uu), bF1=__ldg(b1+Un+u0+uu), bG1=__ldg(b1+2*Un+u0+uu), bO1=__ldg(b1+3*Un+u0+uu);

    float a00[4], a01[4], a10[4], a11[4];
    uint4 aH[2], aL[2], bH[2], bL[2];
    unsigned gen = 0;

    auto compute_tile = [&](int q){
        unsigned sb = sbase + q*(BUFEL*2);
#pragma unroll
        for (int kk=0; kk<KT; kk+=16){
            unsigned bh[4], bl[4], ah[4], al[4];
            unsigned addrB = sb + (unsigned)((OFF_BHI + (n0w+laneB_n)*ROWS72 + kk + laneB_k)*2);
            ldsm4(bh, addrB);
            ldsm4(bl, addrB + (OFF_BLO-OFF_BHI)*2);
            unsigned addrA = sb + (unsigned)(((rowbase+laneA_row)*ROWS72 + kk + laneA_k)*2);
            ldsm4(ah, addrA);
            ldsm4(al, addrA + OFF_ALO*2);
            mma16816(a00, ah, bh);   mma16816(a00, al, bh);   mma16816(a00, ah, bl);
            mma16816(a01, ah, bh+2); mma16816(a01, al, bh+2); mma16816(a01, ah, bl+2);
            addrA += 16*ROWS72*2;
            ldsm4(ah, addrA);
            ldsm4(al, addrA + OFF_ALO*2);
            mma16816(a10, ah, bh);   mma16816(a10, al, bh);   mma16816(a10, ah, bl);
            mma16816(a11, ah, bh+2); mma16816(a11, al, bh+2); mma16816(a11, ah, bl+2);
        }
    };
    auto stsq = [&](int q){
        __nv_bfloat16* bp = s_bf + q*BUFEL;
#pragma unroll
        for (int p=0;p<2;p++){
            int row = rr + 32*p;
            *reinterpret_cast<uint4*>(bp + OFF_AHI + row*ROWS72 + 8*ko) = aH[p];
            *reinterpret_cast<uint4*>(bp + OFF_ALO + row*ROWS72 + 8*ko) = aL[p];
            *reinterpret_cast<uint4*>(bp + OFF_BHI + row*ROWS72 + 8*ko) = bH[p];
            *reinterpret_cast<uint4*>(bp + OFF_BLO + row*ROWS72 + 8*ko) = bL[p];
        }
    };
    auto zacc = [&](){
#pragma unroll
        for (int q=0;q<4;q++){ a00[q]=0.f; a01[q]=0.f; a10[q]=0.f; a11[q]=0.f; }
    };
    auto storeZ = [&](){
        int r0 = rowbase + (lane>>2);
        int c0 = n0w + 2*(lane&3);
        *reinterpret_cast<float2*>(sZf + (r0   )*66 + c0  ) = make_float2(a00[0],a00[1]);
        *reinterpret_cast<float2*>(sZf + (r0+8 )*66 + c0  ) = make_float2(a00[2],a00[3]);
        *reinterpret_cast<float2*>(sZf + (r0   )*66 + c0+8) = make_float2(a01[0],a01[1]);
        *reinterpret_cast<float2*>(sZf + (r0+8 )*66 + c0+8) = make_float2(a01[2],a01[3]);
        *reinterpret_cast<float2*>(sZf + (r0+16)*66 + c0  ) = make_float2(a10[0],a10[1]);
        *reinterpret_cast<float2*>(sZf + (r0+24)*66 + c0  ) = make_float2(a10[2],a10[3]);
        *reinterpret_cast<float2*>(sZf + (r0+16)*66 + c0+8) = make_float2(a11[0],a11[1]);
        *reinterpret_cast<float2*>(sZf + (r0+24)*66 + c0+8) = make_float2(a11[2],a11[3]);
    };

#pragma unroll 1
    for (int t = 0; t < Tt; t++){
        const int ping = t & 1, pong = ping ^ 1;

        // ===== phase A : layer 0 =====
        {
            auto ldgA = [&](int cc){
                if (cc < 16){
                    int k0 = cc*KT;
                    const __nv_bfloat16* hh = g_h0b[ping][0];
                    const __nv_bfloat16* hl = g_h0b[ping][1];
#pragma unroll
                    for (int p=0;p<2;p++){
                        int row = rr + 32*p;
                        aH[p] = *reinterpret_cast<const uint4*>(hh + row*Un + k0 + 8*ko);
                        aL[p] = *reinterpret_cast<const uint4*>(hl + row*Un + k0 + 8*ko);
                        int gn = ((row>>4)<<10) + u0 + (row&15);
                        size_t off = (size_t)gn*Un + k0 + 8*ko;
                        bH[p] = *reinterpret_cast<const uint4*>(g_U0t[0] + off);
                        bL[p] = *reinterpret_cast<const uint4*>(g_U0t[1] + off);
                    }
                } else {
                    int k0 = (cc-16)*KT;
#pragma unroll
                    for (int p=0;p<2;p++){
                        int row = rr + 32*p;
                        const float* xp = x + ((size_t)row*Tt + t)*Fin + k0 + 8*ko;
                        float f[8];
                        *reinterpret_cast<float4*>(f  ) = *reinterpret_cast<const float4*>(xp);
                        *reinterpret_cast<float4*>(f+4) = *reinterpret_cast<const float4*>(xp+4);
                        split8(f, aH[p], aL[p]);
                        int gn = ((row>>4)<<10) + u0 + (row&15);
                        size_t off = (size_t)gn*Fin + k0 + 8*ko;
                        bH[p] = *reinterpret_cast<const uint4*>(g_W0t[0] + off);
                        bL[p] = *reinterpret_cast<const uint4*>(g_W0t[1] + off);
                    }
                }
            };
            zacc();
            ldgA(0); stsq(0);
            __syncthreads();
#pragma unroll 1
            for (int cc=0; cc<18; cc++){
                if (cc+1 < 18) ldgA(cc+1);
                compute_tile(cc&1);
                if (cc+1 < 18) stsq((cc+1)&1);
                __syncthreads();
            }
            storeZ();
            __syncthreads();
#pragma unroll
            for (int it=0; it<4; it++){
                int r = (tid>>4) + 16*it;
                const float* zr = sZf + r*66;
                float gi=sigm(zr[uu]+bI0), gf=sigm(zr[16+uu]+bF0);
                float gg=tanhf(zr[32+uu]+bG0), go=sigm(zr[48+uu]+bO0);
                int gidx = r*Un + u0 + uu;
                float cn = gf*g_c0[gidx] + gi*gg;
                g_c0[gidx] = cn;
                float h = go*tanhf(cn);
                __nv_bfloat16 hh = __float2bfloat16(h);
                g_h0b[pong][0][gidx] = hh;
                g_h0b[pong][1][gidx] = __float2bfloat16(h - __bfloat162float(hh));
                float s=h, q=h*h;
#pragma unroll
                for (int o=8;o;o>>=1){
                    s += __shfl_down_sync(0xffffffffu, s, o, 16);
                    q += __shfl_down_sync(0xffffffffu, q, o, 16);
                }
                if (uu == 0) g_part0[r*GRID + b] = make_float2(s,q);
            }
        }
        gridbar(gen);

        // ===== phase B : LN(h0) + layer 1 =====
        {
#pragma unroll
            for (int j=0;j<8;j++){
                int r = warp*8 + j;
                float4 A4 = reinterpret_cast<const float4*>(g_part0 + r*GRID)[lane];
                float s = A4.x + A4.z, q = A4.y + A4.w;
#pragma unroll
                for (int o=16;o;o>>=1){
                    s += __shfl_down_sync(0xffffffffu, s, o);
                    q += __shfl_down_sync(0xffffffffu, q, o);
                }
                if (lane == 0){
                    float mu  = s * (1.f/1024.f);
                    float var = fmaxf(q * (1.f/1024.f) - mu*mu, 0.f);
                    s_mu[r] = mu; s_rs[r] = rsqrtf(var + 1e-3f);
                }
            }
            __syncthreads();

            auto ldgB = [&](int cc){
                if (cc < 16){
                    int k0 = cc*KT;
                    const __nv_bfloat16* hh = g_h1b[ping][0];
                    const __nv_bfloat16* hl = g_h1b[ping][1];
#pragma unroll
                    for (int p=0;p<2;p++){
                        int row = rr + 32*p;
                        aH[p] = *reinterpret_cast<const uint4*>(hh + row*Un + k0 + 8*ko);
                        aL[p] = *reinterpret_cast<const uint4*>(hl + row*Un + k0 + 8*ko);
                        int gn = ((row>>4)<<10) + u0 + (row&15);
                        size_t off = (size_t)gn*Un + k0 + 8*ko;
                        bH[p] = *reinterpret_cast<const uint4*>(g_U1t[0] + off);
                        bL[p] = *reinterpret_cast<const uint4*>(g_U1t[1] + off);
                    }
                } else {
                    int k0 = (cc-16)*KT;
                    float gv[8], bv[8];
                    *reinterpret_cast<float4*>(gv  ) = *reinterpret_cast<const float4*>(g0  + k0 + 8*ko);
                    *reinterpret_cast<float4*>(gv+4) = *reinterpret_cast<const float4*>(g0  + k0 + 8*ko + 4);
                    *reinterpret_cast<float4*>(bv  ) = *reinterpret_cast<const float4*>(be0 + k0 + 8*ko);
                    *reinterpret_cast<float4*>(bv+4) = *reinterpret_cast<const float4*>(be0 + k0 + 8*ko + 4);
                    const __nv_bfloat16* hh = g_h0b[pong][0];
                    const __nv_bfloat16* hl = g_h0b[pong][1];
#pragma unroll
                    for (int p=0;p<2;p++){
                        int row = rr + 32*p;
                        uint4 H = *reinterpret_cast<const uint4*>(hh + row*Un + k0 + 8*ko);
                        uint4 L = *reinterpret_cast<const uint4*>(hl + row*Un + k0 + 8*ko);
                        float f[8], fl[8];
                        up2(H.x,f[0],f[1]); up2(H.y,f[2],f[3]); up2(H.z,f[4],f[5]); up2(H.w,f[6],f[7]);
                        up2(L.x,fl[0],fl[1]); up2(L.y,fl[2],fl[3]); up2(L.z,fl[4],fl[5]); up2(L.w,fl[6],fl[7]);
                        float mu = s_mu[row], rs = s_rs[row];
#pragma unroll
                        for (int i=0;i<8;i++) f[i] = ((f[i]+fl[i]) - mu)*rs*gv[i] + bv[i];
                        split8(f, aH[p], aL[p]);
                        int gn = ((row>>4)<<10) + u0 + (row&15);
                        size_t off = (size_t)gn*Un + k0 + 8*ko;
                        bH[p] = *reinterpret_cast<const uint4*>(g_W1t[0] + off);
                        bL[p] = *reinterpret_cast<const uint4*>(g_W1t[1] + off);
                    }
                }
            };
            zacc();
            ldgB(0); stsq(0);
            __syncthreads();
#pragma unroll 1
            for (int cc=0; cc<32; cc++){
                if (cc+1 < 32) ldgB(cc+1);
                compute_tile(cc&1);
                if (cc+1 < 32) stsq((cc+1)&1);
                __syncthreads();
            }
            storeZ();
            __syncthreads();
#pragma unroll
            for (int it=0; it<4; it++){
                int r = (tid>>4) + 16*it;
                const float* zr = sZf + r*66;
                float gi=sigm(zr[uu]+bI1), gf=sigm(zr[16+uu]+bF1);
                float gg=tanhf(zr[32+uu]+bG1), go=sigm(zr[48+uu]+bO1);
                int gidx = r*Un + u0 + uu;
                float cn = gf*g_c1[gidx] + gi*gg;
                g_c1[gidx] = cn;
                float h = go*tanhf(cn);
                __nv_bfloat16 hh = __float2bfloat16(h);
                g_h1b[pong][0][gidx] = hh;
                g_h1b[pong][1][gidx] = __float2bfloat16(h - __bfloat162float(hh));
                g_h1f[gidx] = h;
                float s=h, q=h*h;
#pragma unroll
                for (int o=8;o;o>>=1){
                    s += __shfl_down_sync(0xffffffffu, s, o, 16);
                    q += __shfl_down_sync(0xffffffffu, q, o, 16);
                }
                if (uu == 0) g_part1[r*GRID + b] = make_float2(s,q);
            }
        }
        gridbar(gen);

        // ===== phase C : LN(h1) + FC + softmax (block b = batch row b) =====
        {
            float* sO = sZf;
            const float* h = g_h1f + b*Un;
            float v[4];
#pragma unroll
            for (int i=0;i<4;i++) v[i] = h[tid + i*256];
            if (warp == 0){
                float4 A4 = reinterpret_cast<const float4*>(g_part1 + b*GRID)[lane];
                float s = A4.x + A4.z, q = A4.y + A4.w;
#pragma unroll
                for (int o=16;o;o>>=1){
                    s += __shfl_down_sync(0xffffffffu, s, o);
                    q += __shfl_down_sync(0xffffffffu, q, o);
                }
                if (lane == 0){
                    float mu  = s * (1.f/1024.f);
                    float var = fmaxf(q * (1.f/1024.f) - mu*mu, 0.f);
                    s_st[0] = mu; s_st[1] = rsqrtf(var + 1e-3f);
                }
            }
            __syncthreads();
            float mu = s_st[0], rs = s_st[1];
#pragma unroll
            for (int i=0;i<4;i++){
                int k = tid + i*256;
                sO[k] = (v[i]-mu)*rs*__ldg(g1+k) + __ldg(be1+k);
            }
            __syncthreads();
            {
                float l0 = 0.f, l1 = 0.f;
#pragma unroll 4
                for (int k=lane; k<Un; k+=32){
                    float o = sO[k];
                    l0 += o * __ldg(Wfc + k*NCLS + 2*warp);
                    l1 += o * __ldg(Wfc + k*NCLS + 2*warp + 1);
                }
#pragma unroll
                for (int o=16;o;o>>=1){
                    l0 += __shfl_down_sync(0xffffffffu, l0, o);
                    l1 += __shfl_down_sync(0xffffffffu, l1, o);
                }
                if (lane == 0){
                    s_logit[2*warp]   = l0 + __ldg(bfc + 2*warp);
                    s_logit[2*warp+1] = l1 + __ldg(bfc + 2*warp+1);
                }
            }
            __syncthreads();
            if (tid < NCLS){
                float m = -1e30f;
#pragma unroll
                for (int j=0;j<NCLS;j++) m = fmaxf(m, s_logit[j]);
                float ss = 0.f;
#pragma unroll
                for (int j=0;j<NCLS;j++) ss += expf(s_logit[j]-m);
                out[((size_t)b*Tt + t)*NCLS + tid] = expf(s_logit[tid]-m) / ss;
            }
            __syncthreads();
        }
    }
}

extern "C" void kernel_launch(void* const* d_in, const int* in_sizes, int n_in,
                              void* d_out, int out_size)
{
    const float* x   = (const float*)d_in[0];
    const float* W0  = (const float*)d_in[1];
    const float* U0  = (const float*)d_in[2];
    const float* b0  = (const float*)d_in[3];
    const float* g0  = (const float*)d_in[4];
    const float* be0 = (const float*)d_in[5];
    const float* W1  = (const float*)d_in[6];
    const float* U1  = (const float*)d_in[7];
    const float* b1  = (const float*)d_in[8];
    const float* g1  = (const float*)d_in[9];
    const float* be1 = (const float*)d_in[10];
    const float* Wfc = (const float*)d_in[11];
    const float* bfc = (const float*)d_in[12];
    float* out = (float*)d_out;

    static bool attrSet = false;
    if (!attrSet){
        cudaFuncSetAttribute(lstm_persistent,
            cudaFuncAttributeMaxDynamicSharedMemorySize, SMEM_DYN);
        attrSet = true;
    }

    initState<<<128, 512>>>();
    dim3 thr(32, 8);
    prepSplit<<<dim3(G4/32, Un/32), thr>>>(U0, Un, 0);
    prepSplit<<<dim3(G4/32, Un/32), thr>>>(W1, Un, 1);
    prepSplit<<<dim3(G4/32, Un/32), thr>>>(U1, Un, 2);
    prepSplit<<<dim3(G4/32, Fin/32), thr>>>(W0, Fin, 3);
    lstm_persistent<<<GRID, 256, SMEM_DYN>>>(x, b0, g0, be0, b1, g1, be1, Wfc, bfc, out);
}